// round 3
// baseline (speedup 1.0000x reference)
#include <cuda_runtime.h>
#include <cuda_bf16.h>

// SSIM loss, fully fused. (1,3,2048,2048) fp32, VALID 11-tap separable Gaussian
// (sigma=1.5). Output scalar fp32 = 1 - mean(ssim_map) over (3,2038,2038).
//
// v3: 32x64 tiles (halo amortization), 16-row-per-thread vertical blur
// (less LDS), deterministic fixed-point atomic reduction (no 13us tail kernel).

#define H_DIM 2048
#define W_DIM 2048
#define OUT_DIM 2038
#define TILE_W 32
#define TILE_H 64
#define IN_W 42            // TILE_W + 10
#define IN_H 74            // TILE_H + 10
#define NTHREADS 128
#define SXY_STRIDE 43      // conflict-free: (11q+8s+k)%32 has no collisions
#define HB_STRIDE 33       // conflict-free: (q+8s)%32 covers 0..31
#define GRID_X 64          // 64*32 = 2048 >= 2038
#define GRID_Y 32          // 32*64 = 2048 >= 2038

// floats: sx,sy = 2*74*43 ; hb = 5*74*33
#define SMEM_FLOATS (2 * IN_H * SXY_STRIDE + 5 * IN_H * HB_STRIDE)
#define SMEM_BYTES (SMEM_FLOATS * 4)

// Normalized gaussian(sigma=1.5, size=11); sum == 1.0f.
#define W0 0.00102841f
#define W1 0.00759878f
#define W2 0.03600077f
#define W3 0.10936067f
#define W4 0.21300553f
#define W5 0.26601168f

#define FIXED_SCALE 16777216.0   // 2^24

__device__ unsigned long long g_accum = 0ull;

// NOUT 11-tap dot products over an (NOUT+10)-wide window; weights become
// FFMA-imm (rt_SMSP=1) in SASS.
template <int NOUT>
__device__ __forceinline__ void convN(const float* __restrict__ v,
                                      float* __restrict__ acc) {
    const float W[11] = {W0, W1, W2, W3, W4, W5, W4, W3, W2, W1, W0};
    #pragma unroll
    for (int j = 0; j < NOUT; ++j) {
        float a = W0 * v[j];
        #pragma unroll
        for (int t = 1; t < 11; ++t)
            a = fmaf(W[t], v[j + t], a);
        acc[j] = a;
    }
}

__global__ __launch_bounds__(NTHREADS)
void ssim_main_kernel(const float* __restrict__ xin, const float* __restrict__ yin) {
    extern __shared__ float smem[];
    float* sx = smem;                               // [IN_H][43]
    float* sy = sx + IN_H * SXY_STRIDE;             // [IN_H][43]
    float* hb = sy + IN_H * SXY_STRIDE;             // [5][IN_H][33]
    __shared__ float red[4];

    const int tid = threadIdx.x;
    const int gx0 = blockIdx.x * TILE_W;
    const int gy0 = blockIdx.y * TILE_H;
    const float* __restrict__ xp = xin + (size_t)blockIdx.z * (H_DIM * W_DIM);
    const float* __restrict__ yp = yin + (size_t)blockIdx.z * (H_DIM * W_DIM);

    // ---- Load 74x42 x,y tile (zero clamp at image edge) ----
    for (int i = tid; i < IN_H * IN_W; i += NTHREADS) {
        int r = i / IN_W;
        int c = i - r * IN_W;
        int gr = gy0 + r;
        int gc = gx0 + c;
        float xv = 0.0f, yv = 0.0f;
        if (gr < H_DIM && gc < W_DIM) {
            int idx = gr * W_DIM + gc;
            xv = __ldg(xp + idx);
            yv = __ldg(yp + idx);
        }
        sx[r * SXY_STRIDE + c] = xv;
        sy[r * SXY_STRIDE + c] = yv;
    }
    __syncthreads();

    // ---- Phase A: horizontal blur of 5 maps; 74 rows x 4 runs of 8 = 296 tasks ----
    for (int task = tid; task < IN_H * 4; task += NTHREADS) {
        int r  = task >> 2;
        int c0 = (task & 3) << 3;
        const float* sxr = sx + r * SXY_STRIDE + c0;
        const float* syr = sy + r * SXY_STRIDE + c0;
        float* hbr = hb + r * HB_STRIDE + c0;
        float xw[18], yw[18], pw[18], acc[8];

        #pragma unroll
        for (int k = 0; k < 18; ++k) xw[k] = sxr[k];
        convN<8>(xw, acc);
        #pragma unroll
        for (int j = 0; j < 8; ++j) hbr[0 * IN_H * HB_STRIDE + j] = acc[j];

        #pragma unroll
        for (int k = 0; k < 18; ++k) yw[k] = syr[k];
        convN<8>(yw, acc);
        #pragma unroll
        for (int j = 0; j < 8; ++j) hbr[1 * IN_H * HB_STRIDE + j] = acc[j];

        #pragma unroll
        for (int k = 0; k < 18; ++k) pw[k] = xw[k] * xw[k];
        convN<8>(pw, acc);
        #pragma unroll
        for (int j = 0; j < 8; ++j) hbr[2 * IN_H * HB_STRIDE + j] = acc[j];

        #pragma unroll
        for (int k = 0; k < 18; ++k) pw[k] = yw[k] * yw[k];
        convN<8>(pw, acc);
        #pragma unroll
        for (int j = 0; j < 8; ++j) hbr[3 * IN_H * HB_STRIDE + j] = acc[j];

        #pragma unroll
        for (int k = 0; k < 18; ++k) pw[k] = xw[k] * yw[k];
        convN<8>(pw, acc);
        #pragma unroll
        for (int j = 0; j < 8; ++j) hbr[4 * IN_H * HB_STRIDE + j] = acc[j];
    }
    __syncthreads();

    // ---- Phase B: vertical blur (16 rows/thread) + SSIM + reduce ----
    const int tx  = tid & 31;            // output column
    const int tg  = tid >> 5;            // warp id: rows [tg*16, tg*16+16)
    const int oyb = tg << 4;

    float acc[5][16];
    #pragma unroll
    for (int m = 0; m < 5; ++m) {
        const float* col = hb + m * IN_H * HB_STRIDE + oyb * HB_STRIDE + tx;
        float v[26];
        #pragma unroll
        for (int k = 0; k < 26; ++k) v[k] = col[k * HB_STRIDE];
        convN<16>(v, acc[m]);
    }

    const float C1 = 0.01f * 0.01f;
    const float C2 = 0.03f * 0.03f;
    float lsum = 0.0f;
    const int ox = gx0 + tx;
    #pragma unroll
    for (int j = 0; j < 16; ++j) {
        int oy = gy0 + oyb + j;
        if (oy < OUT_DIM && ox < OUT_DIM) {
            float mu1 = acc[0][j], mu2 = acc[1][j];
            float m11 = mu1 * mu1;
            float m22 = mu2 * mu2;
            float m12 = mu1 * mu2;
            float s1  = acc[2][j] - m11;
            float s2  = acc[3][j] - m22;
            float s12 = acc[4][j] - m12;
            float num = (2.0f * m12 + C1) * (2.0f * s12 + C2);
            float den = (m11 + m22 + C1) * (s1 + s2 + C2);
            lsum += __fdividef(num, den);
        }
    }

    #pragma unroll
    for (int off = 16; off > 0; off >>= 1)
        lsum += __shfl_down_sync(0xffffffffu, lsum, off);
    if (tx == 0) red[tg] = lsum;
    __syncthreads();
    if (tid == 0) {
        double bs = (double)(red[0] + red[1] + red[2] + red[3]);
        unsigned long long q = (unsigned long long)__double2ll_rn(bs * FIXED_SCALE);
        atomicAdd(&g_accum, q);   // integer adds: order-independent => deterministic
    }
}

__global__ void ssim_final_kernel(float* __restrict__ out) {
    unsigned long long v = g_accum;
    g_accum = 0ull;   // reset for next graph replay
    double mean = ((double)v / FIXED_SCALE) / (3.0 * (double)OUT_DIM * (double)OUT_DIM);
    out[0] = 1.0f - (float)mean;
}

extern "C" void kernel_launch(void* const* d_in, const int* in_sizes, int n_in,
                              void* d_out, int out_size) {
    const float* pred = (const float*)d_in[0];
    const float* targ = (const float*)d_in[1];
    float* out = (float*)d_out;

    cudaFuncSetAttribute(ssim_main_kernel,
                         cudaFuncAttributeMaxDynamicSharedMemorySize, SMEM_BYTES);

    dim3 grid(GRID_X, GRID_Y, 3);
    ssim_main_kernel<<<grid, NTHREADS, SMEM_BYTES>>>(pred, targ);
    ssim_final_kernel<<<1, 1>>>(out);
}